// round 13
// baseline (speedup 1.0000x reference)
#include <cuda_runtime.h>
#include <cuda_fp16.h>
#include <cstdint>

#define N_NODES 100000
#define N_EDGES 3200000
#define IN_SIZE 256
#define HID_SIZE 256
#define OUT_SIZE 64

// -------- scratch (no allocations allowed -> __device__ globals) --------
// 1024B alignment so every 128B feature line is cache-line contained.
__device__ __align__(1024) __half g_xw1[(size_t)N_NODES * HID_SIZE];  // X @ W1
__device__ __align__(1024) __half g_h  [(size_t)N_NODES * HID_SIZE];  // relu(A@XW1+b1)
__device__ __align__(1024) __half g_hw2[(size_t)N_NODES * OUT_SIZE];  // h @ W2
__device__ __align__(1024) __half g_w1t[(size_t)HID_SIZE * IN_SIZE];  // W1^T [n][k]
__device__ __align__(1024) __half g_w2t[(size_t)OUT_SIZE * HID_SIZE]; // W2^T [n][k]
__device__ int    g_rowptr[N_NODES + 1];

// -------- CSR row_ptr from sorted COO row[]: per-node lower_bound --------
__global__ void build_rowptr_kernel(const int* __restrict__ row) {
    int r = blockIdx.x * blockDim.x + threadIdx.x;
    if (r > N_NODES) return;
    int lo = 0, hi = N_EDGES;
    while (lo < hi) {
        int mid = (lo + hi) >> 1;
        if (row[mid] < r) lo = mid + 1; else hi = mid;
    }
    g_rowptr[r] = lo;
}

// -------- weight transpose+convert: W[k][n] fp32 -> Wt[n][k] fp16 --------
__global__ void wprep_kernel(const float* __restrict__ W1,
                             const float* __restrict__ W2) {
    int idx = blockIdx.x * 256 + threadIdx.x;   // grid covers 256*256
    {   // W1: 256x256, idx = k*256 + n
        int k = idx >> 8, n = idx & 255;
        g_w1t[(size_t)n * IN_SIZE + k] = __float2half(W1[idx]);
    }
    if (idx < HID_SIZE * OUT_SIZE) {   // W2: 256x64, idx = k*64 + n
        int k = idx >> 6, n = idx & 63;
        g_w2t[(size_t)n * HID_SIZE + k] = __float2half(W2[idx]);
    }
}

// -------- fp16 tensor-core GEMM: C[M,N] = A[M,K] @ Bt^T, fp32 accum ------
__device__ __forceinline__ void mma_h16(float* d, const uint32_t* a, const uint32_t* b) {
    asm volatile(
        "mma.sync.aligned.m16n8k16.row.col.f32.f16.f16.f32 "
        "{%0,%1,%2,%3}, {%4,%5,%6,%7}, {%8,%9}, {%0,%1,%2,%3};\n"
        : "+f"(d[0]), "+f"(d[1]), "+f"(d[2]), "+f"(d[3])
        : "r"(a[0]), "r"(a[1]), "r"(a[2]), "r"(a[3]),
          "r"(b[0]), "r"(b[1]));
}

__device__ __forceinline__ void ldsm_x4(uint32_t* r, const __half* p) {
    uint32_t sa = (uint32_t)__cvta_generic_to_shared(p);
    asm volatile("ldmatrix.sync.aligned.m8n8.x4.shared.b16 {%0,%1,%2,%3}, [%4];"
        : "=r"(r[0]), "=r"(r[1]), "=r"(r[2]), "=r"(r[3]) : "r"(sa));
}

// BM x BN tile, BK=32, 256 threads = 8 warps (4 x 2), double-buffered smem.
// A: [M,K] (fp32 or fp16), Bt: [N][K] fp16 (pre-transposed weights).
template<int BM, int BN, int N_DIM, int K_DIM, typename TA>
__global__ __launch_bounds__(256)
void h16_gemm_kernel(int M,
                     const TA* __restrict__ A,
                     const __half* __restrict__ Bt,
                     __half* __restrict__ C) {
    constexpr int BK = 32;
    constexpr int WARPS_M = 4, WARPS_N = 2;
    constexpr int MT = BM / (WARPS_M * 16);   // 2
    constexpr int NT = BN / (WARPS_N * 8);    // 8 (BN=128) or 4 (BN=64)
    constexpr int AST = BK + 8;               // 40-half stride: conflict-free
    constexpr int T = K_DIM / BK;             // 8 k-tiles
    constexpr bool A_F32 = (sizeof(TA) == 4);
    constexpr int A_LD_F = BM * BK / (4 * 256);   // float4/thread (fp32 A): 4
    constexpr int A_LD_H = BM * BK / (8 * 256);   // uint4/thread  (fp16 A): 2
    constexpr int B_LD   = BN * BK / (8 * 256);   // uint4/thread: 2 or 1

    __shared__ __half As[2][BM * AST];
    __shared__ __half Bs[2][BN * AST];

    const int tid  = threadIdx.x;
    const int lane = tid & 31;
    const int wid  = tid >> 5;
    const int warp_m = wid % WARPS_M;
    const int warp_n = wid / WARPS_M;
    const int g  = lane >> 2;
    const int tg = lane & 3;
    const int ri = lane & 7;     // ldmatrix row-in-matrix
    const int mi = lane >> 3;    // ldmatrix matrix index 0..3

    const int rowBase = blockIdx.y * BM;
    const int colBase = blockIdx.x * BN;
    const int aRow = warp_m * (MT * 16);
    const int bCol = warp_n * (NT * 8);

    float4 afr[A_F32 ? A_LD_F : 1];
    uint4  ahr[A_F32 ? 1 : A_LD_H];
    uint4  bhr[B_LD];

    float acc[MT][NT][4];
    #pragma unroll
    for (int i = 0; i < MT; i++)
        #pragma unroll
        for (int j = 0; j < NT; j++)
            #pragma unroll
            for (int q = 0; q < 4; q++) acc[i][j][q] = 0.f;

    auto ldgA = [&](int t) {
        int k0 = t * BK;
        if constexpr (A_F32) {
            #pragma unroll
            for (int i = 0; i < A_LD_F; i++) {
                int idx = tid + i * 256;
                int m = idx >> 3, q = idx & 7;      // 8 float4 per 32-wide row
                int gr = rowBase + m;
                afr[i] = (gr < M)
                    ? *(const float4*)((const float*)A + (size_t)gr * K_DIM + k0 + q * 4)
                    : make_float4(0.f, 0.f, 0.f, 0.f);
            }
        } else {
            #pragma unroll
            for (int i = 0; i < A_LD_H; i++) {
                int idx = tid + i * 256;
                int m = idx >> 2, q = idx & 3;      // 4 uint4 per 32-half row
                int gr = rowBase + m;
                ahr[i] = (gr < M)
                    ? *(const uint4*)((const __half*)A + (size_t)gr * K_DIM + k0 + q * 8)
                    : make_uint4(0u, 0u, 0u, 0u);
            }
        }
    };
    auto stsA = [&](int b) {
        if constexpr (A_F32) {
            #pragma unroll
            for (int i = 0; i < A_LD_F; i++) {
                int idx = tid + i * 256;
                int m = idx >> 3, q = idx & 7;
                union { uint2 u; __half2 h[2]; } pk;
                pk.h[0] = __floats2half2_rn(afr[i].x, afr[i].y);
                pk.h[1] = __floats2half2_rn(afr[i].z, afr[i].w);
                *(uint2*)&As[b][m * AST + q * 4] = pk.u;
            }
        } else {
            #pragma unroll
            for (int i = 0; i < A_LD_H; i++) {
                int idx = tid + i * 256;
                int m = idx >> 2, q = idx & 3;
                *(uint2*)&As[b][m * AST + q * 8]     = make_uint2(ahr[i].x, ahr[i].y);
                *(uint2*)&As[b][m * AST + q * 8 + 4] = make_uint2(ahr[i].z, ahr[i].w);
            }
        }
    };
    auto ldgB = [&](int t) {
        int k0 = t * BK;
        #pragma unroll
        for (int i = 0; i < B_LD; i++) {
            int idx = tid + i * 256;
            int n = idx >> 2, q = idx & 3;
            bhr[i] = *(const uint4*)(Bt + (size_t)(colBase + n) * K_DIM + k0 + q * 8);
        }
    };
    auto stsB = [&](int b) {
        #pragma unroll
        for (int i = 0; i < B_LD; i++) {
            int idx = tid + i * 256;
            int n = idx >> 2, q = idx & 3;
            *(uint2*)&Bs[b][n * AST + q * 8]     = make_uint2(bhr[i].x, bhr[i].y);
            *(uint2*)&Bs[b][n * AST + q * 8 + 4] = make_uint2(bhr[i].z, bhr[i].w);
        }
    };
    auto compute = [&](int b) {
        #pragma unroll
        for (int kk = 0; kk < BK; kk += 16) {
            uint32_t af[MT][4];
            #pragma unroll
            for (int mt = 0; mt < MT; mt++) {
                const __half* ap = &As[b][(aRow + mt * 16 + ((mi & 1) << 3) + ri) * AST
                                          + kk + ((mi >> 1) << 3)];
                ldsm_x4(af[mt], ap);
            }
            uint32_t bf[NT][2];
            #pragma unroll
            for (int p = 0; p < NT / 2; p++) {
                const __half* bp = &Bs[b][(bCol + p * 16 + ((mi >> 1) << 3) + ri) * AST
                                          + kk + ((mi & 1) << 3)];
                uint32_t r4[4];
                ldsm_x4(r4, bp);
                bf[p * 2][0] = r4[0]; bf[p * 2][1] = r4[1];
                bf[p * 2 + 1][0] = r4[2]; bf[p * 2 + 1][1] = r4[3];
            }
            #pragma unroll
            for (int nt = 0; nt < NT; nt++)
                #pragma unroll
                for (int mt = 0; mt < MT; mt++)
                    mma_h16(acc[mt][nt], af[mt], bf[nt]);
        }
    };

    // ---- double-buffered mainloop ----
    ldgA(0); ldgB(0);
    stsA(0); stsB(0);
    __syncthreads();
    ldgA(1); ldgB(1);

    #pragma unroll 2
    for (int t = 0; t < T; t++) {
        compute(t & 1);
        if (t + 1 < T) { stsA((t + 1) & 1); stsB((t + 1) & 1); }
        __syncthreads();
        if (t + 2 < T) { ldgA(t + 2); ldgB(t + 2); }
    }

    // ---- epilogue: fp32 acc -> fp16 ----
    #pragma unroll
    for (int mt = 0; mt < MT; mt++) {
        int r0 = rowBase + aRow + mt * 16 + g;
        #pragma unroll
        for (int nt = 0; nt < NT; nt++) {
            int c = colBase + bCol + nt * 8 + tg * 2;
            if (r0 < M) {
                __half2 v = __floats2half2_rn(acc[mt][nt][0], acc[mt][nt][1]);
                *(__half2*)(C + (size_t)r0 * N_DIM + c) = v;
            }
            if (r0 + 8 < M) {
                __half2 v = __floats2half2_rn(acc[mt][nt][2], acc[mt][nt][3]);
                *(__half2*)(C + (size_t)(r0 + 8) * N_DIM + c) = v;
            }
        }
    }
}

// -------- SpMM layer 1: h = relu(A @ g_xw1 + b1) -------------------------
// One warp per row, 8 rows per block. Line-split gather: per edge, FOUR
// LDG.32 instructions, each covering exactly one 128B line (32 lanes x 4B),
// so wavefronts stream at the cross-LDG 1.0/cyc rate instead of the 2.07
// within-LDG replay rate. Lane owns features l*64 + lane*2 (+1), l=0..3.
// Same hfma2 chains + fp32 flush every 8 edges -> bit-identical results.
__global__ __launch_bounds__(256)
void spmm1_kernel(const float* __restrict__ ev,
                  const int* __restrict__ col,
                  const float* __restrict__ b1) {
    const int lane = threadIdx.x & 31;
    const int r = blockIdx.x * 8 + (threadIdx.x >> 5);
    const int e0 = g_rowptr[r], e1 = g_rowptr[r + 1];

    float acc[8];
    #pragma unroll
    for (int i = 0; i < 8; i++) acc[i] = 0.f;
    __half2 hacc[4];
    #pragma unroll
    for (int i = 0; i < 4; i++) hacc[i] = __float2half2_rn(0.f);

    // base for line l of row c: g_xw1 + c*256 + l*64 + lane*2  (half2 units)
    const __half2* base = (const __half2*)g_xw1 + lane;
    int e = e0;
    for (; e + 8 <= e1; e += 8) {
        #pragma unroll
        for (int j = 0; j < 8; j++) {
            float v = ev[e + j]; int c = col[e + j];
            __half2 v2 = __float2half2_rn(v);
            const __half2* p = base + (size_t)c * (HID_SIZE / 2);
            __half2 q0 = p[0];
            __half2 q1 = p[32];
            __half2 q2 = p[64];
            __half2 q3 = p[96];
            hacc[0] = __hfma2(q0, v2, hacc[0]);
            hacc[1] = __hfma2(q1, v2, hacc[1]);
            hacc[2] = __hfma2(q2, v2, hacc[2]);
            hacc[3] = __hfma2(q3, v2, hacc[3]);
        }
        #pragma unroll
        for (int i = 0; i < 4; i++) {
            float2 f = __half22float2(hacc[i]);
            acc[2 * i] += f.x; acc[2 * i + 1] += f.y;
            hacc[i] = __float2half2_rn(0.f);
        }
    }
    for (; e < e1; e++) {
        float v = ev[e]; int c = col[e];
        __half2 v2 = __float2half2_rn(v);
        const __half2* p = base + (size_t)c * (HID_SIZE / 2);
        __half2 q0 = p[0];
        __half2 q1 = p[32];
        __half2 q2 = p[64];
        __half2 q3 = p[96];
        hacc[0] = __hfma2(q0, v2, hacc[0]);
        hacc[1] = __hfma2(q1, v2, hacc[1]);
        hacc[2] = __hfma2(q2, v2, hacc[2]);
        hacc[3] = __hfma2(q3, v2, hacc[3]);
    }
    #pragma unroll
    for (int i = 0; i < 4; i++) {
        float2 f = __half22float2(hacc[i]);
        acc[2 * i] += f.x; acc[2 * i + 1] += f.y;
    }

    // epilogue: feature pair for slot l lives at l*64 + lane*2
    __half2* outp = (__half2*)(g_h + (size_t)r * HID_SIZE) + lane;
    #pragma unroll
    for (int i = 0; i < 4; i++) {
        float2 bb = *(const float2*)(b1 + i * 64 + lane * 2);
        float h0 = acc[2 * i]     + bb.x;
        float h1 = acc[2 * i + 1] + bb.y;
        h0 = h0 > 0.f ? h0 : 0.f;
        h1 = h1 > 0.f ? h1 : 0.f;
        outp[i * 32] = __floats2half2_rn(h0, h1);
    }
}

// -------- SpMM layer 2: out = A @ g_hw2 + b2 (fp32 accum) ----------------
// One warp per row (32 lanes x half2 = 64 features = one 128B line/edge),
// 8 rows per block; aligned 4-edge batches with 4 gathers in flight.
__global__ __launch_bounds__(256)
void spmm2_kernel(const float* __restrict__ ev,
                  const int* __restrict__ col,
                  const float* __restrict__ b2,
                  float* __restrict__ out) {
    const int lane = threadIdx.x & 31;
    const int r = blockIdx.x * 8 + (threadIdx.x >> 5);
    const int e0 = g_rowptr[r], e1 = g_rowptr[r + 1];

    float ax = 0.f, ay = 0.f;
    const __half2* base = (const __half2*)(g_hw2) + lane;

    int e = e0;
    int ea = (e0 + 3) & ~3;
    if (ea > e1) ea = e1;
    for (; e < ea; e++) {
        float v = ev[e];
        float2 f = __half22float2(base[(size_t)col[e] * (OUT_SIZE / 2)]);
        ax += v * f.x; ay += v * f.y;
    }
    for (; e + 4 <= e1; e += 4) {
        int4   c4 = *(const int4*)(col + e);
        float4 v4 = *(const float4*)(ev + e);
        __half2 h0 = base[(size_t)c4.x * (OUT_SIZE / 2)];
        __half2 h1 = base[(size_t)c4.y * (OUT_SIZE / 2)];
        __half2 h2 = base[(size_t)c4.z * (OUT_SIZE / 2)];
        __half2 h3 = base[(size_t)c4.w * (OUT_SIZE / 2)];
        float2 f0 = __half22float2(h0);
        float2 f1 = __half22float2(h1);
        float2 f2 = __half22float2(h2);
        float2 f3 = __half22float2(h3);
        ax += v4.x * f0.x; ay += v4.x * f0.y;
        ax += v4.y * f1.x; ay += v4.y * f1.y;
        ax += v4.z * f2.x; ay += v4.z * f2.y;
        ax += v4.w * f3.x; ay += v4.w * f3.y;
    }
    for (; e < e1; e++) {
        float v = ev[e];
        float2 f = __half22float2(base[(size_t)col[e] * (OUT_SIZE / 2)]);
        ax += v * f.x; ay += v * f.y;
    }

    float2 o;
    o.x = ax + b2[lane * 2];
    o.y = ay + b2[lane * 2 + 1];
    *(float2*)(out + (size_t)r * OUT_SIZE + lane * 2) = o;
}

extern "C" void kernel_launch(void* const* d_in, const int* in_sizes, int n_in,
                              void* d_out, int out_size) {
    const float* X   = (const float*)d_in[0];
    const float* ev  = (const float*)d_in[1];
    const float* W1  = (const float*)d_in[2];
    const float* b1  = (const float*)d_in[3];
    const float* W2  = (const float*)d_in[4];
    const float* b2  = (const float*)d_in[5];
    const int*   row = (const int*)  d_in[6];
    const int*   col = (const int*)  d_in[7];
    float* out = (float*)d_out;

    void *p_xw1 = nullptr, *p_h = nullptr, *p_hw2 = nullptr;
    void *p_w1t = nullptr, *p_w2t = nullptr;
    cudaGetSymbolAddress(&p_xw1, g_xw1);
    cudaGetSymbolAddress(&p_h,   g_h);
    cudaGetSymbolAddress(&p_hw2, g_hw2);
    cudaGetSymbolAddress(&p_w1t, g_w1t);
    cudaGetSymbolAddress(&p_w2t, g_w2t);

    // 1) row_ptr + weight transpose/convert
    {
        int threads = 256;
        int blocks = (N_NODES + 1 + threads - 1) / threads;
        build_rowptr_kernel<<<blocks, threads>>>(row);
        wprep_kernel<<<(IN_SIZE * HID_SIZE) / 256, 256>>>(W1, W2);
    }

    // 2) g_xw1 = X @ W1   (M=100000, N=256, K=256)  fp16 MMA + ldmatrix
    {
        dim3 grid(HID_SIZE / 128, (N_NODES + 127) / 128);
        h16_gemm_kernel<128, 128, HID_SIZE, IN_SIZE, float><<<grid, 256>>>(
            N_NODES, X, (const __half*)p_w1t, (__half*)p_xw1);
    }

    // 3) g_h = relu(A @ g_xw1 + b1)   warp-per-row, line-split gather
    spmm1_kernel<<<N_NODES / 8, 256>>>(ev, col, b1);

    // 4) g_hw2 = g_h @ W2   (M=100000, N=64, K=256)  fp16 MMA + ldmatrix
    {
        dim3 grid(OUT_SIZE / 64, (N_NODES + 127) / 128);
        h16_gemm_kernel<128, 64, OUT_SIZE, HID_SIZE, __half><<<grid, 256>>>(
            N_NODES, (const __half*)p_h, (const __half*)p_w2t, (__half*)p_hw2);
    }

    // 5) out = A @ g_hw2 + b2   warp-per-row, MLP-4 gather
    spmm2_kernel<<<N_NODES / 8, 256>>>(ev, col, b2, out);
}

// round 14
// speedup vs baseline: 1.1026x; 1.1026x over previous
#include <cuda_runtime.h>
#include <cuda_fp16.h>
#include <cstdint>

#define N_NODES 100000
#define N_EDGES 3200000
#define IN_SIZE 256
#define HID_SIZE 256
#define OUT_SIZE 64

// -------- scratch (no allocations allowed -> __device__ globals) --------
__device__ __align__(1024) __half g_xw1[(size_t)N_NODES * HID_SIZE];  // X @ W1
__device__ __align__(1024) __half g_h  [(size_t)N_NODES * HID_SIZE];  // relu(A@XW1+b1)
__device__ __align__(1024) __half g_hw2[(size_t)N_NODES * OUT_SIZE];  // h @ W2
__device__ __align__(1024) __half g_w1t[(size_t)HID_SIZE * IN_SIZE];  // W1^T [n][k]
__device__ __align__(1024) __half g_w2t[(size_t)OUT_SIZE * HID_SIZE]; // W2^T [n][k]
__device__ int    g_rowptr[N_NODES + 1];

// -------- CSR row_ptr from sorted COO row[]: per-node lower_bound --------
__global__ void build_rowptr_kernel(const int* __restrict__ row) {
    int r = blockIdx.x * blockDim.x + threadIdx.x;
    if (r > N_NODES) return;
    int lo = 0, hi = N_EDGES;
    while (lo < hi) {
        int mid = (lo + hi) >> 1;
        if (row[mid] < r) lo = mid + 1; else hi = mid;
    }
    g_rowptr[r] = lo;
}

// -------- weight transpose+convert: W[k][n] fp32 -> Wt[n][k] fp16 --------
__global__ void wprep_kernel(const float* __restrict__ W1,
                             const float* __restrict__ W2) {
    int idx = blockIdx.x * 256 + threadIdx.x;   // grid covers 256*256
    {   // W1: 256x256, idx = k*256 + n
        int k = idx >> 8, n = idx & 255;
        g_w1t[(size_t)n * IN_SIZE + k] = __float2half(W1[idx]);
    }
    if (idx < HID_SIZE * OUT_SIZE) {   // W2: 256x64, idx = k*64 + n
        int k = idx >> 6, n = idx & 63;
        g_w2t[(size_t)n * HID_SIZE + k] = __float2half(W2[idx]);
    }
}

// -------- common MMA helpers ---------------------------------------------
__device__ __forceinline__ void mma_h16(float* d, const uint32_t* a, const uint32_t* b) {
    asm volatile(
        "mma.sync.aligned.m16n8k16.row.col.f32.f16.f16.f32 "
        "{%0,%1,%2,%3}, {%4,%5,%6,%7}, {%8,%9}, {%0,%1,%2,%3};\n"
        : "+f"(d[0]), "+f"(d[1]), "+f"(d[2]), "+f"(d[3])
        : "r"(a[0]), "r"(a[1]), "r"(a[2]), "r"(a[3]),
          "r"(b[0]), "r"(b[1]));
}

__device__ __forceinline__ void ldsm_x4(uint32_t* r, const __half* p) {
    uint32_t sa = (uint32_t)__cvta_generic_to_shared(p);
    asm volatile("ldmatrix.sync.aligned.m8n8.x4.shared.b16 {%0,%1,%2,%3}, [%4];"
        : "=r"(r[0]), "=r"(r[1]), "=r"(r[2]), "=r"(r[3]) : "r"(sa));
}

__device__ __forceinline__ void cp16(void* smem_dst, const void* gmem_src) {
    uint32_t d = (uint32_t)__cvta_generic_to_shared(smem_dst);
    asm volatile("cp.async.cg.shared.global [%0], [%1], 16;\n" :: "r"(d), "l"(gmem_src));
}

// ============ GEMM1: inline fp32->fp16 convert, double-buffered (R10) ====
// BM x BN tile, BK=32, 256 threads = 8 warps (4 x 2).
template<int BM, int BN, int N_DIM, int K_DIM>
__global__ __launch_bounds__(256)
void h16_gemm_kernel(int M,
                     const float* __restrict__ A,
                     const __half* __restrict__ Bt,
                     __half* __restrict__ C) {
    constexpr int BK = 32;
    constexpr int WARPS_M = 4, WARPS_N = 2;
    constexpr int MT = BM / (WARPS_M * 16);   // 2
    constexpr int NT = BN / (WARPS_N * 8);    // 8
    constexpr int AST = BK + 8;               // 40-half stride: conflict-free
    constexpr int T = K_DIM / BK;             // 8 k-tiles
    constexpr int A_LD_F = BM * BK / (4 * 256);   // float4/thread: 4
    constexpr int B_LD   = BN * BK / (8 * 256);   // uint4/thread: 2

    __shared__ __half As[2][BM * AST];
    __shared__ __half Bs[2][BN * AST];

    const int tid  = threadIdx.x;
    const int lane = tid & 31;
    const int wid  = tid >> 5;
    const int warp_m = wid % WARPS_M;
    const int warp_n = wid / WARPS_M;
    const int g  = lane >> 2;
    const int tg = lane & 3;
    const int ri = lane & 7;
    const int mi = lane >> 3;

    const int rowBase = blockIdx.y * BM;
    const int colBase = blockIdx.x * BN;
    const int aRow = warp_m * (MT * 16);
    const int bCol = warp_n * (NT * 8);

    float4 afr[A_LD_F];
    uint4  bhr[B_LD];

    float acc[MT][NT][4];
    #pragma unroll
    for (int i = 0; i < MT; i++)
        #pragma unroll
        for (int j = 0; j < NT; j++)
            #pragma unroll
            for (int q = 0; q < 4; q++) acc[i][j][q] = 0.f;

    auto ldgA = [&](int t) {
        int k0 = t * BK;
        #pragma unroll
        for (int i = 0; i < A_LD_F; i++) {
            int idx = tid + i * 256;
            int m = idx >> 3, q = idx & 7;
            int gr = rowBase + m;
            afr[i] = (gr < M)
                ? *(const float4*)(A + (size_t)gr * K_DIM + k0 + q * 4)
                : make_float4(0.f, 0.f, 0.f, 0.f);
        }
    };
    auto stsA = [&](int b) {
        #pragma unroll
        for (int i = 0; i < A_LD_F; i++) {
            int idx = tid + i * 256;
            int m = idx >> 3, q = idx & 7;
            union { uint2 u; __half2 h[2]; } pk;
            pk.h[0] = __floats2half2_rn(afr[i].x, afr[i].y);
            pk.h[1] = __floats2half2_rn(afr[i].z, afr[i].w);
            *(uint2*)&As[b][m * AST + q * 4] = pk.u;
        }
    };
    auto ldgB = [&](int t) {
        int k0 = t * BK;
        #pragma unroll
        for (int i = 0; i < B_LD; i++) {
            int idx = tid + i * 256;
            int n = idx >> 2, q = idx & 3;
            bhr[i] = *(const uint4*)(Bt + (size_t)(colBase + n) * K_DIM + k0 + q * 8);
        }
    };
    auto stsB = [&](int b) {
        #pragma unroll
        for (int i = 0; i < B_LD; i++) {
            int idx = tid + i * 256;
            int n = idx >> 2, q = idx & 3;
            *(uint2*)&Bs[b][n * AST + q * 8]     = make_uint2(bhr[i].x, bhr[i].y);
            *(uint2*)&Bs[b][n * AST + q * 8 + 4] = make_uint2(bhr[i].z, bhr[i].w);
        }
    };
    auto compute = [&](int b) {
        #pragma unroll
        for (int kk = 0; kk < BK; kk += 16) {
            uint32_t af[MT][4];
            #pragma unroll
            for (int mt = 0; mt < MT; mt++) {
                const __half* ap = &As[b][(aRow + mt * 16 + ((mi & 1) << 3) + ri) * AST
                                          + kk + ((mi >> 1) << 3)];
                ldsm_x4(af[mt], ap);
            }
            uint32_t bf[NT][2];
            #pragma unroll
            for (int p = 0; p < NT / 2; p++) {
                const __half* bp = &Bs[b][(bCol + p * 16 + ((mi >> 1) << 3) + ri) * AST
                                          + kk + ((mi & 1) << 3)];
                uint32_t r4[4];
                ldsm_x4(r4, bp);
                bf[p * 2][0] = r4[0]; bf[p * 2][1] = r4[1];
                bf[p * 2 + 1][0] = r4[2]; bf[p * 2 + 1][1] = r4[3];
            }
            #pragma unroll
            for (int nt = 0; nt < NT; nt++)
                #pragma unroll
                for (int mt = 0; mt < MT; mt++)
                    mma_h16(acc[mt][nt], af[mt], bf[nt]);
        }
    };

    ldgA(0); ldgB(0);
    stsA(0); stsB(0);
    __syncthreads();
    ldgA(1); ldgB(1);

    #pragma unroll 2
    for (int t = 0; t < T; t++) {
        compute(t & 1);
        if (t + 1 < T) { stsA((t + 1) & 1); stsB((t + 1) & 1); }
        __syncthreads();
        if (t + 2 < T) { ldgA(t + 2); ldgB(t + 2); }
    }

    #pragma unroll
    for (int mt = 0; mt < MT; mt++) {
        int r0 = rowBase + aRow + mt * 16 + g;
        #pragma unroll
        for (int nt = 0; nt < NT; nt++) {
            int c = colBase + bCol + nt * 8 + tg * 2;
            if (r0 < M) {
                __half2 v = __floats2half2_rn(acc[mt][nt][0], acc[mt][nt][1]);
                *(__half2*)(C + (size_t)r0 * N_DIM + c) = v;
            }
            if (r0 + 8 < M) {
                __half2 v = __floats2half2_rn(acc[mt][nt][2], acc[mt][nt][3]);
                *(__half2*)(C + (size_t)(r0 + 8) * N_DIM + c) = v;
            }
        }
    }
}

// ============ GEMM2: all-fp16, 4-stage cp.async pipeline (R11 form) ======
constexpr int GEMM_STAGES = 4;
constexpr int GEMM_BK = 32;
constexpr int GEMM_AST = GEMM_BK + 8;
constexpr size_t gemm_smem_bytes(int BM, int BN) {
    return (size_t)GEMM_STAGES * (BM + BN) * GEMM_AST * 2;
}

template<int BM, int BN, int N_DIM, int K_DIM>
__global__ __launch_bounds__(256)
void h16_gemm_async(int M,
                    const __half* __restrict__ A,
                    const __half* __restrict__ Bt,
                    __half* __restrict__ C) {
    constexpr int BK = GEMM_BK;
    constexpr int STAGES = GEMM_STAGES;
    constexpr int WARPS_M = 4, WARPS_N = 2;
    constexpr int MT = BM / (WARPS_M * 16);   // 2
    constexpr int NT = BN / (WARPS_N * 8);    // 4 for BN=64
    constexpr int AST = GEMM_AST;
    constexpr int T = K_DIM / BK;             // 8
    constexpr int A_CH = BM * 4 / 256;        // 2
    constexpr int B_CH = BN * 4 / 256;        // 1

    extern __shared__ __half smem[];
    __half* Asm = smem;
    __half* Bsm = smem + (size_t)STAGES * BM * AST;

    const int tid  = threadIdx.x;
    const int lane = tid & 31;
    const int wid  = tid >> 5;
    const int warp_m = wid % WARPS_M;
    const int warp_n = wid / WARPS_M;
    const int g  = lane >> 2;
    const int tg = lane & 3;
    const int ri = lane & 7;
    const int mi = lane >> 3;

    const int rowBase = blockIdx.y * BM;
    const int colBase = blockIdx.x * BN;
    const int aRow = warp_m * (MT * 16);
    const int bCol = warp_n * (NT * 8);

    float acc[MT][NT][4];
    #pragma unroll
    for (int i = 0; i < MT; i++)
        #pragma unroll
        for (int j = 0; j < NT; j++)
            #pragma unroll
            for (int q = 0; q < 4; q++) acc[i][j][q] = 0.f;

    auto issue = [&](int t) {
        int s = t % STAGES;
        int k0 = t * BK;
        __half* Ad = Asm + (size_t)s * (BM * AST);
        __half* Bd = Bsm + (size_t)s * (BN * AST);
        #pragma unroll
        for (int i = 0; i < A_CH; i++) {
            int idx = tid + i * 256;
            int m = idx >> 2, q = idx & 3;
            int gr = rowBase + m;
            if (gr >= M) gr = M - 1;   // clamped read; epilogue guards stores
            cp16(Ad + m * AST + q * 8, A + (size_t)gr * K_DIM + k0 + q * 8);
        }
        #pragma unroll
        for (int i = 0; i < B_CH; i++) {
            int idx = tid + i * 256;
            int n = idx >> 2, q = idx & 3;
            cp16(Bd + n * AST + q * 8, Bt + (size_t)(colBase + n) * K_DIM + k0 + q * 8);
        }
    };

    auto compute = [&](int s) {
        const __half* Ab = Asm + (size_t)s * (BM * AST);
        const __half* Bb = Bsm + (size_t)s * (BN * AST);
        #pragma unroll
        for (int kk = 0; kk < BK; kk += 16) {
            uint32_t af[MT][4];
            #pragma unroll
            for (int mt = 0; mt < MT; mt++) {
                const __half* ap = &Ab[(aRow + mt * 16 + ((mi & 1) << 3) + ri) * AST
                                       + kk + ((mi >> 1) << 3)];
                ldsm_x4(af[mt], ap);
            }
            uint32_t bf[NT][2];
            #pragma unroll
            for (int p = 0; p < NT / 2; p++) {
                const __half* bp = &Bb[(bCol + p * 16 + ((mi >> 1) << 3) + ri) * AST
                                       + kk + ((mi & 1) << 3)];
                uint32_t r4[4];
                ldsm_x4(r4, bp);
                bf[p * 2][0] = r4[0]; bf[p * 2][1] = r4[1];
                bf[p * 2 + 1][0] = r4[2]; bf[p * 2 + 1][1] = r4[3];
            }
            #pragma unroll
            for (int nt = 0; nt < NT; nt++)
                #pragma unroll
                for (int mt = 0; mt < MT; mt++)
                    mma_h16(acc[mt][nt], af[mt], bf[nt]);
        }
    };

    issue(0); asm volatile("cp.async.commit_group;\n" ::);
    issue(1); asm volatile("cp.async.commit_group;\n" ::);
    issue(2); asm volatile("cp.async.commit_group;\n" ::);

    #pragma unroll 4
    for (int t = 0; t < T; t++) {
        asm volatile("cp.async.wait_group 2;\n" ::);
        __syncthreads();
        if (t + 3 < T) issue(t + 3);
        asm volatile("cp.async.commit_group;\n" ::);
        compute(t % STAGES);
    }

    #pragma unroll
    for (int mt = 0; mt < MT; mt++) {
        int r0 = rowBase + aRow + mt * 16 + g;
        #pragma unroll
        for (int nt = 0; nt < NT; nt++) {
            int c = colBase + bCol + nt * 8 + tg * 2;
            if (r0 < M) {
                __half2 v = __floats2half2_rn(acc[mt][nt][0], acc[mt][nt][1]);
                *(__half2*)(C + (size_t)r0 * N_DIM + c) = v;
            }
            if (r0 + 8 < M) {
                __half2 v = __floats2half2_rn(acc[mt][nt][2], acc[mt][nt][3]);
                *(__half2*)(C + (size_t)(r0 + 8) * N_DIM + c) = v;
            }
        }
    }
}

// -------- SpMM layer 1: h = relu(A @ g_xw1 + b1) (R10 best form) ---------
__global__ __launch_bounds__(256)
void spmm1_kernel(const float* __restrict__ ev,
                  const int* __restrict__ col,
                  const float* __restrict__ b1) {
    const int lane = threadIdx.x & 31;
    const int r = blockIdx.x * 8 + (threadIdx.x >> 5);
    const int e0 = g_rowptr[r], e1 = g_rowptr[r + 1];

    float acc[8];
    #pragma unroll
    for (int i = 0; i < 8; i++) acc[i] = 0.f;
    __half2 hacc[4];
    #pragma unroll
    for (int i = 0; i < 4; i++) hacc[i] = __float2half2_rn(0.f);

    const __half* base = g_xw1 + lane * 8;
    int e = e0;
    for (; e + 8 <= e1; e += 8) {
        #pragma unroll
        for (int j = 0; j < 8; j++) {
            float v = ev[e + j]; int c = col[e + j];
            __half2 v2 = __float2half2_rn(v);
            uint4 q = *(const uint4*)(base + (size_t)c * HID_SIZE);
            __half2* h = (__half2*)&q;
            hacc[0] = __hfma2(h[0], v2, hacc[0]);
            hacc[1] = __hfma2(h[1], v2, hacc[1]);
            hacc[2] = __hfma2(h[2], v2, hacc[2]);
            hacc[3] = __hfma2(h[3], v2, hacc[3]);
        }
        #pragma unroll
        for (int i = 0; i < 4; i++) {
            float2 f = __half22float2(hacc[i]);
            acc[2 * i] += f.x; acc[2 * i + 1] += f.y;
            hacc[i] = __float2half2_rn(0.f);
        }
    }
    for (; e < e1; e++) {
        float v = ev[e]; int c = col[e];
        __half2 v2 = __float2half2_rn(v);
        uint4 q = *(const uint4*)(base + (size_t)c * HID_SIZE);
        __half2* h = (__half2*)&q;
        hacc[0] = __hfma2(h[0], v2, hacc[0]);
        hacc[1] = __hfma2(h[1], v2, hacc[1]);
        hacc[2] = __hfma2(h[2], v2, hacc[2]);
        hacc[3] = __hfma2(h[3], v2, hacc[3]);
    }
    #pragma unroll
    for (int i = 0; i < 4; i++) {
        float2 f = __half22float2(hacc[i]);
        acc[2 * i] += f.x; acc[2 * i + 1] += f.y;
    }

    __half2 o[4];
    #pragma unroll
    for (int i = 0; i < 4; i++) {
        float h0 = acc[2 * i]     + b1[lane * 8 + 2 * i];
        float h1 = acc[2 * i + 1] + b1[lane * 8 + 2 * i + 1];
        h0 = h0 > 0.f ? h0 : 0.f;
        h1 = h1 > 0.f ? h1 : 0.f;
        o[i] = __floats2half2_rn(h0, h1);
    }
    *(uint4*)(g_h + (size_t)r * HID_SIZE + lane * 8) = *(uint4*)o;
}

// -------- SpMM layer 2: out = A @ g_hw2 + b2 -----------------------------
// One warp per row (32 lanes x half2 = 64 features), 8 rows per block.
// HFMA2 accumulation (1 cvt + 1 hfma2 per edge), fp32 flush every 8 edges.
__global__ __launch_bounds__(256)
void spmm2_kernel(const float* __restrict__ ev,
                  const int* __restrict__ col,
                  const float* __restrict__ b2,
                  float* __restrict__ out) {
    const int lane = threadIdx.x & 31;
    const int r = blockIdx.x * 8 + (threadIdx.x >> 5);
    const int e0 = g_rowptr[r], e1 = g_rowptr[r + 1];

    float ax = 0.f, ay = 0.f;
    __half2 hacc = __float2half2_rn(0.f);
    const __half2* base = (const __half2*)(g_hw2) + lane;

    auto flush = [&]() {
        float2 f = __half22float2(hacc);
        ax += f.x; ay += f.y;
        hacc = __float2half2_rn(0.f);
    };

    int e = e0;
    for (; e + 8 <= e1; e += 8) {
        #pragma unroll
        for (int j = 0; j < 8; j++) {
            float v = ev[e + j]; int c = col[e + j];
            __half2 v2 = __float2half2_rn(v);
            __half2 q = base[(size_t)c * (OUT_SIZE / 2)];
            hacc = __hfma2(q, v2, hacc);
        }
        flush();
    }
    for (; e < e1; e++) {
        float v = ev[e]; int c = col[e];
        __half2 v2 = __float2half2_rn(v);
        __half2 q = base[(size_t)c * (OUT_SIZE / 2)];
        hacc = __hfma2(q, v2, hacc);
    }
    flush();

    float2 o;
    o.x = ax + b2[lane * 2];
    o.y = ay + b2[lane * 2 + 1];
    *(float2*)(out + (size_t)r * OUT_SIZE + lane * 2) = o;
}

extern "C" void kernel_launch(void* const* d_in, const int* in_sizes, int n_in,
                              void* d_out, int out_size) {
    const float* X   = (const float*)d_in[0];
    const float* ev  = (const float*)d_in[1];
    const float* W1  = (const float*)d_in[2];
    const float* b1  = (const float*)d_in[3];
    const float* W2  = (const float*)d_in[4];
    const float* b2  = (const float*)d_in[5];
    const int*   row = (const int*)  d_in[6];
    const int*   col = (const int*)  d_in[7];
    float* out = (float*)d_out;

    void *p_xw1 = nullptr, *p_h = nullptr, *p_hw2 = nullptr;
    void *p_w1t = nullptr, *p_w2t = nullptr;
    cudaGetSymbolAddress(&p_xw1, g_xw1);
    cudaGetSymbolAddress(&p_h,   g_h);
    cudaGetSymbolAddress(&p_hw2, g_hw2);
    cudaGetSymbolAddress(&p_w1t, g_w1t);
    cudaGetSymbolAddress(&p_w2t, g_w2t);

    constexpr size_t SMEM2 = gemm_smem_bytes(128, 64);   // 61440 B
    cudaFuncSetAttribute(h16_gemm_async<128, 64, OUT_SIZE, HID_SIZE>,
                         cudaFuncAttributeMaxDynamicSharedMemorySize, (int)SMEM2);

    // 1) row_ptr + weight transpose/convert
    {
        int threads = 256;
        int blocks = (N_NODES + 1 + threads - 1) / threads;
        build_rowptr_kernel<<<blocks, threads>>>(row);
        wprep_kernel<<<(IN_SIZE * HID_SIZE) / 256, 256>>>(W1, W2);
    }

    // 2) g_xw1 = X @ W1   (M=100000, N=256, K=256)  inline-convert fp16 MMA
    {
        dim3 grid(HID_SIZE / 128, (N_NODES + 127) / 128);
        h16_gemm_kernel<128, 128, HID_SIZE, IN_SIZE><<<grid, 256>>>(
            N_NODES, X, (const __half*)p_w1t, (__half*)p_xw1);
    }

    // 3) g_h = relu(A @ g_xw1 + b1)   warp-per-row HFMA2 gather (best form)
    spmm1_kernel<<<N_NODES / 8, 256>>>(ev, col, b1);

    // 4) g_hw2 = g_h @ W2   (M=100000, N=64, K=256)  4-stage cp.async fp16
    {
        dim3 grid(OUT_SIZE / 64, (N_NODES + 127) / 128);
        h16_gemm_async<128, 64, OUT_SIZE, HID_SIZE><<<grid, 256, SMEM2>>>(
            N_NODES, (const __half*)p_h, (const __half*)p_w2t, (__half*)p_hw2);
    }

    // 5) out = A @ g_hw2 + b2   warp-per-row HFMA2 gather
    spmm2_kernel<<<N_NODES / 8, 256>>>(ev, col, b2, out);
}